// round 12
// baseline (speedup 1.0000x reference)
#include <cuda_runtime.h>
#include <cuda_bf16.h>
#include <cuda_fp16.h>
#include <cstdint>
#include <stdint.h>
#include <math.h>

// ---------------------------------------------------------------------------
// Transformer encoder block, fp16 tensor-core path (m16n8k16 mma, fp32 accum).
// GEMM: 3-stage cp.async pipeline, single barrier per k-tile.
// (tcgen05 unavailable: harness targets sm_100 without the 'a' feature set.)
// B=4, S=2048, D=1024, H=16, d_k=64, FFN=4096
// ---------------------------------------------------------------------------

#define D_MODEL 1024
#define N_HEADS 16
#define D_K     64
#define D_FF    4096
#define SEQ     2048
#define BATCH   4
#define M_ROWS  (BATCH * SEQ)          // 8192

// fp32 scratch
__device__ float g_prj[M_ROWS * D_MODEL];
__device__ float g_h  [M_ROWS * D_MODEL];
__device__ float g_f  [M_ROWS * D_MODEL];
// fp16 scratch
__device__ __half g_x16 [M_ROWS * D_MODEL];
__device__ __half g_Wq16[D_MODEL * D_MODEL];
__device__ __half g_Wk16[D_MODEL * D_MODEL];
__device__ __half g_Wv16[D_MODEL * D_MODEL];
__device__ __half g_Wo16[D_MODEL * D_MODEL];
__device__ __half g_W116[D_MODEL * D_FF];
__device__ __half g_W216[D_FF * D_MODEL];
__device__ __half g_Q16 [M_ROWS * D_MODEL];
__device__ __half g_K16 [M_ROWS * D_MODEL];
__device__ __half g_V16 [M_ROWS * D_MODEL];
__device__ __half g_ctx [M_ROWS * D_MODEL];
__device__ __half g_h16 [M_ROWS * D_MODEL];
__device__ __half g_mid [(size_t)M_ROWS * D_FF];

// ---------------------------------------------------------------------------
// primitives
// ---------------------------------------------------------------------------
__device__ __forceinline__ void cp16(uint32_t s, const void* g) {
    asm volatile("cp.async.cg.shared.global [%0], [%1], 16;\n" :: "r"(s), "l"(g));
}
__device__ __forceinline__ void cp_commit() {
    asm volatile("cp.async.commit_group;\n" ::: "memory");
}

__device__ __forceinline__ void mma_f16(
    float& c0, float& c1, float& c2, float& c3,
    uint32_t a0, uint32_t a1, uint32_t a2, uint32_t a3,
    uint32_t b0, uint32_t b1)
{
    asm volatile(
        "mma.sync.aligned.m16n8k16.row.col.f32.f16.f16.f32 "
        "{%0,%1,%2,%3}, {%4,%5,%6,%7}, {%8,%9}, {%0,%1,%2,%3};\n"
        : "+f"(c0), "+f"(c1), "+f"(c2), "+f"(c3)
        : "r"(a0), "r"(a1), "r"(a2), "r"(a3), "r"(b0), "r"(b1));
}

__device__ __forceinline__ void ldsm_x4(uint32_t& r0, uint32_t& r1,
                                        uint32_t& r2, uint32_t& r3, uint32_t a) {
    asm volatile("ldmatrix.sync.aligned.m8n8.x4.shared.b16 {%0,%1,%2,%3}, [%4];"
                 : "=r"(r0), "=r"(r1), "=r"(r2), "=r"(r3) : "r"(a));
}
__device__ __forceinline__ void ldsm_x2(uint32_t& r0, uint32_t& r1, uint32_t a) {
    asm volatile("ldmatrix.sync.aligned.m8n8.x2.shared.b16 {%0,%1}, [%2];"
                 : "=r"(r0), "=r"(r1) : "r"(a));
}
__device__ __forceinline__ void ldsm_x2_t(uint32_t& r0, uint32_t& r1, uint32_t a) {
    asm volatile("ldmatrix.sync.aligned.m8n8.x2.trans.shared.b16 {%0,%1}, [%2];"
                 : "=r"(r0), "=r"(r1) : "r"(a));
}

// ---------------------------------------------------------------------------
// fp32 -> fp16 conversion (weights + x), once per launch
// ---------------------------------------------------------------------------
__global__ __launch_bounds__(256) void cvt16_kernel(
    const float* __restrict__ s, __half* __restrict__ d, int n)
{
    int i = (blockIdx.x * 256 + threadIdx.x) * 4;
    if (i < n) {
        float4 v = *(const float4*)(s + i);
        *(__half2*)(d + i)     = __floats2half2_rn(v.x, v.y);
        *(__half2*)(d + i + 2) = __floats2half2_rn(v.z, v.w);
    }
}

// ---------------------------------------------------------------------------
// FP16 GEMM: C[M,N] = A[M,K] @ B[K,N] + bias (+ReLU) (C fp32 or fp16)
// BM=128, BN=128, BK=32, 256 threads (8 warps), warp tile 64x32,
// mma m16n8k16, ldmatrix fragments, 3-stage cp.async pipeline,
// single __syncthreads per k-tile.
// ---------------------------------------------------------------------------
#define A_STR 40
#define B_STR 136
#define A_ELE (128 * A_STR)   // 5120 halfs
#define B_ELE (32  * B_STR)   // 4352 halfs
#define STG_ELE (A_ELE + B_ELE)               // 9472 halfs
#define GEMM_SMEM_BYTES (3 * STG_ELE * 2)     // 56832 bytes

__global__ __launch_bounds__(256) void gemm_f16_kernel(
    const __half* __restrict__ A, const __half* __restrict__ B,
    const float* __restrict__ bias, void* __restrict__ Cout,
    int N, int K, int relu, int half_out)
{
    extern __shared__ __half gsm[];

    const int tid  = threadIdx.x;
    const int lane = tid & 31;
    const int warp = tid >> 5;
    const int wm   = (warp >> 2) * 64;
    const int wn   = (warp & 3) * 32;
    const int r    = lane >> 2;
    const int c    = lane & 3;
    const int bm   = blockIdx.y;
    const int bn   = blockIdx.x;

    const __half* Ab = A + (size_t)bm * 128 * K;
    const __half* Bb = B + (size_t)bn * 128;

    uint32_t asAddr[3], bsAddr[3];
    #pragma unroll
    for (int i = 0; i < 3; i++) {
        asAddr[i] = (uint32_t)__cvta_generic_to_shared(gsm + i * STG_ELE);
        bsAddr[i] = asAddr[i] + A_ELE * 2;
    }

    float acc[4][4][4];
    #pragma unroll
    for (int i = 0; i < 4; i++)
        #pragma unroll
        for (int j = 0; j < 4; j++)
            #pragma unroll
            for (int k = 0; k < 4; k++) acc[i][j][k] = 0.0f;

    const int KT = K / 32;

    auto issue = [&](int kk, int b) {
        #pragma unroll
        for (int i = 0; i < 2; i++) {
            int id = tid + i * 256;
            int ar = id >> 2, ac = (id & 3) * 8;
            cp16(asAddr[b] + (uint32_t)(ar * A_STR + ac) * 2,
                 Ab + (size_t)ar * K + kk + ac);
            int br = id >> 4, bc = (id & 15) * 8;
            cp16(bsAddr[b] + (uint32_t)(br * B_STR + bc) * 2,
                 Bb + (size_t)(kk + br) * N + bc);
        }
        cp_commit();
    };

    // prefetch two stages
    issue(0, 0);
    if (KT > 1) issue(32, 1);

    const int lrow = lane & 15;
    const int lcol = (lane & 16) ? 8 : 0;

    int buf = 0;
    for (int kt = 0; kt < KT; kt++) {
        if (kt + 1 < KT) {
            asm volatile("cp.async.wait_group 1;\n" ::: "memory");
        } else {
            asm volatile("cp.async.wait_group 0;\n" ::: "memory");
        }
        __syncthreads();                  // stage kt visible; all warps past kt-1
        if (kt + 2 < KT) {
            int nb = buf + 2; if (nb >= 3) nb -= 3;
            issue((kt + 2) * 32, nb);
        }

        #pragma unroll
        for (int ks = 0; ks < 2; ks++) {
            const int k0 = ks * 16;
            uint32_t af[4][4], bf[4][2];
            #pragma unroll
            for (int ma = 0; ma < 4; ma++) {
                uint32_t a = asAddr[buf] +
                    (uint32_t)((wm + ma * 16 + lrow) * A_STR + k0 + lcol) * 2;
                ldsm_x4(af[ma][0], af[ma][1], af[ma][2], af[ma][3], a);
            }
            #pragma unroll
            for (int na = 0; na < 4; na++) {
                uint32_t a = bsAddr[buf] +
                    (uint32_t)((k0 + lrow) * B_STR + wn + na * 8) * 2;
                ldsm_x2_t(bf[na][0], bf[na][1], a);
            }
            #pragma unroll
            for (int ma = 0; ma < 4; ma++)
                #pragma unroll
                for (int na = 0; na < 4; na++)
                    mma_f16(acc[ma][na][0], acc[ma][na][1],
                            acc[ma][na][2], acc[ma][na][3],
                            af[ma][0], af[ma][1], af[ma][2], af[ma][3],
                            bf[na][0], bf[na][1]);
        }
        if (++buf >= 3) buf = 0;
    }

    #pragma unroll
    for (int ma = 0; ma < 4; ma++) {
        const int row0 = bm * 128 + wm + ma * 16 + r;
        #pragma unroll
        for (int na = 0; na < 4; na++) {
            const int col = bn * 128 + wn + na * 8 + 2 * c;
            const float bv0 = bias[col];
            const float bv1 = bias[col + 1];
            float v0 = acc[ma][na][0] + bv0;
            float v1 = acc[ma][na][1] + bv1;
            float v2 = acc[ma][na][2] + bv0;
            float v3 = acc[ma][na][3] + bv1;
            if (relu) {
                v0 = fmaxf(v0, 0.f); v1 = fmaxf(v1, 0.f);
                v2 = fmaxf(v2, 0.f); v3 = fmaxf(v3, 0.f);
            }
            if (half_out) {
                __half* C = (__half*)Cout;
                *(__half2*)(C + (size_t)row0 * N + col)       = __floats2half2_rn(v0, v1);
                *(__half2*)(C + (size_t)(row0 + 8) * N + col) = __floats2half2_rn(v2, v3);
            } else {
                float* C = (float*)Cout;
                *(float2*)(C + (size_t)row0 * N + col)       = make_float2(v0, v1);
                *(float2*)(C + (size_t)(row0 + 8) * N + col) = make_float2(v2, v3);
            }
        }
    }
}

// ---------------------------------------------------------------------------
// Flash attention, fp16 mma, fp32 softmax. cp.async double-buffered K/V,
// single __syncthreads per k-tile. (Round-10 structure, unchanged.)
// ---------------------------------------------------------------------------
#define ATT_QT  128
#define ATT_KT  64
#define AKS_STR 72
#define KV_ELE  (ATT_KT * AKS_STR)
#define PS_ELE  (ATT_QT * AKS_STR)
#define ATT_SMEM_BYTES ((4 * KV_ELE + PS_ELE) * 2)   // 55296

__global__ __launch_bounds__(256, 2) void attn_f16_kernel(
    const __half* __restrict__ Q, const __half* __restrict__ K,
    const __half* __restrict__ V, __half* __restrict__ O)
{
    extern __shared__ __half smh[];
    __half* Ksb[2] = { smh,              smh + KV_ELE };
    __half* Vsb[2] = { smh + 2 * KV_ELE, smh + 3 * KV_ELE };
    __half* Ps     = smh + 4 * KV_ELE;

    const int b    = blockIdx.z;
    const int h    = blockIdx.y;
    const int qt   = blockIdx.x;
    const int tid  = threadIdx.x;
    const int lane = tid & 31;
    const int warp = tid >> 5;
    const int r    = lane >> 2;
    const int c    = lane & 3;
    const int wm   = warp * 16;
    const int lrow = lane & 15;
    const int lcol = (lane & 16) ? 8 : 0;

    const size_t qrow0 = (size_t)b * SEQ + (size_t)qt * ATT_QT;
    const __half* Qb = Q + qrow0 * D_MODEL + h * D_K;
    const __half* Kb = K + (size_t)b * SEQ * D_MODEL + h * D_K;
    const __half* Vb = V + (size_t)b * SEQ * D_MODEL + h * D_K;

    uint32_t ksA[2], vsA[2];
    ksA[0] = (uint32_t)__cvta_generic_to_shared(Ksb[0]);
    ksA[1] = (uint32_t)__cvta_generic_to_shared(Ksb[1]);
    vsA[0] = (uint32_t)__cvta_generic_to_shared(Vsb[0]);
    vsA[1] = (uint32_t)__cvta_generic_to_shared(Vsb[1]);
    const uint32_t psB = (uint32_t)__cvta_generic_to_shared(Ps);

    auto issue_kv = [&](int kt, int buf) {
        #pragma unroll
        for (int i = 0; i < 2; i++) {
            int id  = tid + i * 256;
            int row = id >> 3, c8 = (id & 7) * 8;
            const size_t gro = (size_t)(kt * ATT_KT + row) * D_MODEL + c8;
            cp16(ksA[buf] + (uint32_t)(row * AKS_STR + c8) * 2, Kb + gro);
            cp16(vsA[buf] + (uint32_t)(row * AKS_STR + c8) * 2, Vb + gro);
        }
        cp_commit();
    };

    issue_kv(0, 0);

    #pragma unroll
    for (int i = 0; i < 4; i++) {
        int id = tid + i * 256;
        int row = id >> 3, c8 = (id & 7) * 8;
        *(uint4*)&Ps[row * AKS_STR + c8] =
            *(const uint4*)(Qb + (size_t)row * D_MODEL + c8);
    }
    __syncthreads();

    uint32_t qa[4][4];
    #pragma unroll
    for (int ks = 0; ks < 4; ks++) {
        uint32_t a = psB + (uint32_t)((wm + lrow) * AKS_STR + ks * 16 + lcol) * 2;
        ldsm_x4(qa[ks][0], qa[ks][1], qa[ks][2], qa[ks][3], a);
    }

    float oacc[8][4];
    #pragma unroll
    for (int nt = 0; nt < 8; nt++)
        #pragma unroll
        for (int i = 0; i < 4; i++) oacc[nt][i] = 0.0f;

    float m0 = -1e30f, m1 = -1e30f, l0 = 0.0f, l1 = 0.0f;

    const int NT = SEQ / ATT_KT;
    for (int kt = 0; kt < NT; kt++) {
        asm volatile("cp.async.wait_group 0;\n" ::: "memory");
        __syncthreads();
        if (kt + 1 < NT) issue_kv(kt + 1, (kt + 1) & 1);

        const uint32_t ksBuf = ksA[kt & 1];
        const uint32_t vsBuf = vsA[kt & 1];

        float sacc[8][4];
        #pragma unroll
        for (int nt = 0; nt < 8; nt++) {
            sacc[nt][0] = sacc[nt][1] = sacc[nt][2] = sacc[nt][3] = 0.0f;
            #pragma unroll
            for (int ks = 0; ks < 4; ks++) {
                uint32_t addr = ksBuf + (uint32_t)(
                    (nt * 8 + (lane & 7)) * AKS_STR + ks * 16 + ((lane & 8) ? 8 : 0)) * 2;
                uint32_t b0, b1;
                ldsm_x2(b0, b1, addr);
                mma_f16(sacc[nt][0], sacc[nt][1], sacc[nt][2], sacc[nt][3],
                        qa[ks][0], qa[ks][1], qa[ks][2], qa[ks][3], b0, b1);
            }
            sacc[nt][0] *= 0.125f; sacc[nt][1] *= 0.125f;
            sacc[nt][2] *= 0.125f; sacc[nt][3] *= 0.125f;
        }

        float tm0 = -1e30f, tm1 = -1e30f;
        #pragma unroll
        for (int nt = 0; nt < 8; nt++) {
            tm0 = fmaxf(tm0, fmaxf(sacc[nt][0], sacc[nt][1]));
            tm1 = fmaxf(tm1, fmaxf(sacc[nt][2], sacc[nt][3]));
        }
        tm0 = fmaxf(tm0, __shfl_xor_sync(0xffffffffu, tm0, 1));
        tm0 = fmaxf(tm0, __shfl_xor_sync(0xffffffffu, tm0, 2));
        tm1 = fmaxf(tm1, __shfl_xor_sync(0xffffffffu, tm1, 1));
        tm1 = fmaxf(tm1, __shfl_xor_sync(0xffffffffu, tm1, 2));

        const float mn0 = fmaxf(m0, tm0);
        const float mn1 = fmaxf(m1, tm1);
        const float fac0 = __expf(m0 - mn0);
        const float fac1 = __expf(m1 - mn1);
        m0 = mn0; m1 = mn1;

        float ts0 = 0.0f, ts1 = 0.0f;
        #pragma unroll
        for (int nt = 0; nt < 8; nt++) {
            float p0 = __expf(sacc[nt][0] - mn0);
            float p1 = __expf(sacc[nt][1] - mn0);
            float p2 = __expf(sacc[nt][2] - mn1);
            float p3 = __expf(sacc[nt][3] - mn1);
            ts0 += p0 + p1;
            ts1 += p2 + p3;
            const int col = nt * 8 + c * 2;
            *(__half2*)&Ps[(wm + r) * AKS_STR + col]     = __floats2half2_rn(p0, p1);
            *(__half2*)&Ps[(wm + r + 8) * AKS_STR + col] = __floats2half2_rn(p2, p3);
        }
        ts0 += __shfl_xor_sync(0xffffffffu, ts0, 1);
        ts0 += __shfl_xor_sync(0xffffffffu, ts0, 2);
        ts1 += __shfl_xor_sync(0xffffffffu, ts1, 1);
        ts1 += __shfl_xor_sync(0xffffffffu, ts1, 2);
        l0 = l0 * fac0 + ts0;
        l1 = l1 * fac1 + ts1;

        #pragma unroll
        for (int nt = 0; nt < 8; nt++) {
            oacc[nt][0] *= fac0; oacc[nt][1] *= fac0;
            oacc[nt][2] *= fac1; oacc[nt][3] *= fac1;
        }

        __syncwarp();

        #pragma unroll
        for (int ks = 0; ks < 4; ks++) {
            const int k0 = ks * 16;
            uint32_t a0, a1, a2, a3;
            ldsm_x4(a0, a1, a2, a3,
                    psB + (uint32_t)((wm + lrow) * AKS_STR + k0 + lcol) * 2);
            #pragma unroll
            for (int nt = 0; nt < 8; nt++) {
                uint32_t b0, b1;
                ldsm_x2_t(b0, b1,
                          vsBuf + (uint32_t)((k0 + lrow) * AKS_STR + nt * 8) * 2);
                mma_f16(oacc[nt][0], oacc[nt][1], oacc[nt][2], oacc[nt][3],
                        a0, a1, a2, a3, b0, b1);
            }
        }
    }

    const float inv0 = 1.0f / l0;
    const float inv1 = 1.0f / l1;
    __half* Ob = O + qrow0 * D_MODEL + h * D_K;
    #pragma unroll
    for (int nt = 0; nt < 8; nt++) {
        const int col = nt * 8 + c * 2;
        *(__half2*)(Ob + (size_t)(wm + r) * D_MODEL + col) =
            __floats2half2_rn(oacc[nt][0] * inv0, oacc[nt][1] * inv0);
        *(__half2*)(Ob + (size_t)(wm + r + 8) * D_MODEL + col) =
            __floats2half2_rn(oacc[nt][2] * inv1, oacc[nt][3] * inv1);
    }
}

// ---------------------------------------------------------------------------
// Fused residual-add + LayerNorm (+fp16 copy)
// ---------------------------------------------------------------------------
__global__ __launch_bounds__(256) void add_ln_kernel(
    const float* __restrict__ a, const float* __restrict__ b,
    const float* __restrict__ g, const float* __restrict__ beta,
    float* __restrict__ out, __half* __restrict__ out16, int w16)
{
    const int row = blockIdx.x;
    const int tid = threadIdx.x;

    const float4 av = *(const float4*)(a + (size_t)row * D_MODEL + tid * 4);
    const float4 bv = *(const float4*)(b + (size_t)row * D_MODEL + tid * 4);
    float4 v;
    v.x = av.x + bv.x; v.y = av.y + bv.y; v.z = av.z + bv.z; v.w = av.w + bv.w;

    float s  = v.x + v.y + v.z + v.w;
    float sq = v.x * v.x + v.y * v.y + v.z * v.z + v.w * v.w;

    #pragma unroll
    for (int off = 16; off; off >>= 1) {
        s  += __shfl_xor_sync(0xffffffffu, s,  off);
        sq += __shfl_xor_sync(0xffffffffu, sq, off);
    }
    __shared__ float red_s[8], red_q[8];
    if ((tid & 31) == 0) { red_s[tid >> 5] = s; red_q[tid >> 5] = sq; }
    __syncthreads();
    __shared__ float smean, srstd;
    if (tid == 0) {
        float ts = 0.f, tq = 0.f;
        #pragma unroll
        for (int i = 0; i < 8; i++) { ts += red_s[i]; tq += red_q[i]; }
        float mean = ts * (1.0f / D_MODEL);
        float var  = tq * (1.0f / D_MODEL) - mean * mean;
        smean = mean;
        srstd = rsqrtf(var + 1e-5f);
    }
    __syncthreads();
    const float mean = smean, rstd = srstd;

    const float4 gv = *(const float4*)(g    + tid * 4);
    const float4 tv = *(const float4*)(beta + tid * 4);
    float4 o;
    o.x = (v.x - mean) * rstd * gv.x + tv.x;
    o.y = (v.y - mean) * rstd * gv.y + tv.y;
    o.z = (v.z - mean) * rstd * gv.z + tv.z;
    o.w = (v.w - mean) * rstd * gv.w + tv.w;
    *(float4*)(out + (size_t)row * D_MODEL + tid * 4) = o;
    if (w16) {
        *(__half2*)(out16 + (size_t)row * D_MODEL + tid * 4)     = __floats2half2_rn(o.x, o.y);
        *(__half2*)(out16 + (size_t)row * D_MODEL + tid * 4 + 2) = __floats2half2_rn(o.z, o.w);
    }
}

// ---------------------------------------------------------------------------
// Launch
// ---------------------------------------------------------------------------
extern "C" void kernel_launch(void* const* d_in, const int* in_sizes, int n_in,
                              void* d_out, int out_size)
{
    const float* x     = (const float*)d_in[0];
    const float* Wq    = (const float*)d_in[1];
    const float* bq    = (const float*)d_in[2];
    const float* Wk    = (const float*)d_in[3];
    const float* bk    = (const float*)d_in[4];
    const float* Wv    = (const float*)d_in[5];
    const float* bv    = (const float*)d_in[6];
    const float* Wo    = (const float*)d_in[7];
    const float* bo    = (const float*)d_in[8];
    const float* ln1_g = (const float*)d_in[9];
    const float* ln1_b = (const float*)d_in[10];
    const float* W1    = (const float*)d_in[11];
    const float* b1    = (const float*)d_in[12];
    const float* W2    = (const float*)d_in[13];
    const float* b2    = (const float*)d_in[14];
    const float* ln2_g = (const float*)d_in[15];
    const float* ln2_b = (const float*)d_in[16];
    float* out = (float*)d_out;

    float *pPrj, *pH, *pF;
    __half *pX16, *pWq, *pWk, *pWv, *pWo, *pW1, *pW2;
    __half *pQ, *pK, *pV, *pCtx, *pH16, *pMid;
    cudaGetSymbolAddress((void**)&pPrj, g_prj);
    cudaGetSymbolAddress((void**)&pH,   g_h);
    cudaGetSymbolAddress((void**)&pF,   g_f);
    cudaGetSymbolAddress((void**)&pX16, g_x16);
    cudaGetSymbolAddress((void**)&pWq,  g_Wq16);
    cudaGetSymbolAddress((void**)&pWk,  g_Wk16);
    cudaGetSymbolAddress((void**)&pWv,  g_Wv16);
    cudaGetSymbolAddress((void**)&pWo,  g_Wo16);
    cudaGetSymbolAddress((void**)&pW1,  g_W116);
    cudaGetSymbolAddress((void**)&pW2,  g_W216);
    cudaGetSymbolAddress((void**)&pQ,   g_Q16);
    cudaGetSymbolAddress((void**)&pK,   g_K16);
    cudaGetSymbolAddress((void**)&pV,   g_V16);
    cudaGetSymbolAddress((void**)&pCtx, g_ctx);
    cudaGetSymbolAddress((void**)&pH16, g_h16);
    cudaGetSymbolAddress((void**)&pMid, g_mid);

    cudaFuncSetAttribute(gemm_f16_kernel,
                         cudaFuncAttributeMaxDynamicSharedMemorySize,
                         GEMM_SMEM_BYTES);
    cudaFuncSetAttribute(attn_f16_kernel,
                         cudaFuncAttributeMaxDynamicSharedMemorySize,
                         ATT_SMEM_BYTES);

    dim3 blk(256);

    // fp32 -> fp16 conversions
    cvt16_kernel<<<(M_ROWS * D_MODEL) / 1024, blk>>>(x,  pX16, M_ROWS * D_MODEL);
    cvt16_kernel<<<(D_MODEL * D_MODEL) / 1024, blk>>>(Wq, pWq, D_MODEL * D_MODEL);
    cvt16_kernel<<<(D_MODEL * D_MODEL) / 1024, blk>>>(Wk, pWk, D_MODEL * D_MODEL);
    cvt16_kernel<<<(D_MODEL * D_MODEL) / 1024, blk>>>(Wv, pWv, D_MODEL * D_MODEL);
    cvt16_kernel<<<(D_MODEL * D_MODEL) / 1024, blk>>>(Wo, pWo, D_MODEL * D_MODEL);
    cvt16_kernel<<<(D_MODEL * D_FF) / 1024, blk>>>(W1, pW1, D_MODEL * D_FF);
    cvt16_kernel<<<(D_FF * D_MODEL) / 1024, blk>>>(W2, pW2, D_FF * D_MODEL);

    dim3 gProj(D_MODEL / 128, M_ROWS / 128);   // (8, 64)
    dim3 gFF1 (D_FF   / 128, M_ROWS / 128);    // (32, 64)
    dim3 gFF2 (D_MODEL / 128, M_ROWS / 128);
    dim3 gAttn(SEQ / ATT_QT, N_HEADS, BATCH);  // (16, 16, 4)

    // QKV projections (fp16 out)
    gemm_f16_kernel<<<gProj, blk, GEMM_SMEM_BYTES>>>(pX16, pWq, bq, pQ, D_MODEL, D_MODEL, 0, 1);
    gemm_f16_kernel<<<gProj, blk, GEMM_SMEM_BYTES>>>(pX16, pWk, bk, pK, D_MODEL, D_MODEL, 0, 1);
    gemm_f16_kernel<<<gProj, blk, GEMM_SMEM_BYTES>>>(pX16, pWv, bv, pV, D_MODEL, D_MODEL, 0, 1);

    // attention
    attn_f16_kernel<<<gAttn, blk, ATT_SMEM_BYTES>>>(pQ, pK, pV, pCtx);

    // output projection (fp32 out for LN)
    gemm_f16_kernel<<<gProj, blk, GEMM_SMEM_BYTES>>>(pCtx, pWo, bo, pPrj, D_MODEL, D_MODEL, 0, 0);

    // residual + LN1 (fp32 h + fp16 h16)
    add_ln_kernel<<<M_ROWS, blk>>>(pPrj, x, ln1_g, ln1_b, pH, pH16, 1);

    // FFN
    gemm_f16_kernel<<<gFF1, blk, GEMM_SMEM_BYTES>>>(pH16, pW1, b1, pMid, D_FF, D_MODEL, 1, 1);
    gemm_f16_kernel<<<gFF2, blk, GEMM_SMEM_BYTES>>>(pMid, pW2, b2, pF, D_MODEL, D_FF, 0, 0);

    // residual + LN2 -> output (fp32)
    add_ln_kernel<<<M_ROWS, blk>>>(pF, pH, ln2_g, ln2_b, out, pH16, 0);
}

// round 15
// speedup vs baseline: 1.0290x; 1.0290x over previous
#include <cuda_runtime.h>
#include <cuda_bf16.h>
#include <cuda_fp16.h>
#include <cstdint>
#include <stdint.h>
#include <math.h>

// ---------------------------------------------------------------------------
// Transformer encoder block, fp16 tensor-core path (m16n8k16 mma, fp32 accum).
// Attention: register-resident P (S-accum -> A-frag direct), no P smem trip.
// B=4, S=2048, D=1024, H=16, d_k=64, FFN=4096
// ---------------------------------------------------------------------------

#define D_MODEL 1024
#define N_HEADS 16
#define D_K     64
#define D_FF    4096
#define SEQ     2048
#define BATCH   4
#define M_ROWS  (BATCH * SEQ)          // 8192

// fp32 scratch
__device__ float g_prj[M_ROWS * D_MODEL];
__device__ float g_h  [M_ROWS * D_MODEL];
__device__ float g_f  [M_ROWS * D_MODEL];
// fp16 scratch
__device__ __half g_x16 [M_ROWS * D_MODEL];
__device__ __half g_Wq16[D_MODEL * D_MODEL];
__device__ __half g_Wk16[D_MODEL * D_MODEL];
__device__ __half g_Wv16[D_MODEL * D_MODEL];
__device__ __half g_Wo16[D_MODEL * D_MODEL];
__device__ __half g_W116[D_MODEL * D_FF];
__device__ __half g_W216[D_FF * D_MODEL];
__device__ __half g_Q16 [M_ROWS * D_MODEL];
__device__ __half g_K16 [M_ROWS * D_MODEL];
__device__ __half g_V16 [M_ROWS * D_MODEL];
__device__ __half g_ctx [M_ROWS * D_MODEL];
__device__ __half g_h16 [M_ROWS * D_MODEL];
__device__ __half g_mid [(size_t)M_ROWS * D_FF];

// ---------------------------------------------------------------------------
// primitives
// ---------------------------------------------------------------------------
__device__ __forceinline__ void cp16(uint32_t s, const void* g) {
    asm volatile("cp.async.cg.shared.global [%0], [%1], 16;\n" :: "r"(s), "l"(g));
}
__device__ __forceinline__ void cp_commit() {
    asm volatile("cp.async.commit_group;\n" ::: "memory");
}

__device__ __forceinline__ void mma_f16(
    float& c0, float& c1, float& c2, float& c3,
    uint32_t a0, uint32_t a1, uint32_t a2, uint32_t a3,
    uint32_t b0, uint32_t b1)
{
    asm volatile(
        "mma.sync.aligned.m16n8k16.row.col.f32.f16.f16.f32 "
        "{%0,%1,%2,%3}, {%4,%5,%6,%7}, {%8,%9}, {%0,%1,%2,%3};\n"
        : "+f"(c0), "+f"(c1), "+f"(c2), "+f"(c3)
        : "r"(a0), "r"(a1), "r"(a2), "r"(a3), "r"(b0), "r"(b1));
}

__device__ __forceinline__ void ldsm_x4(uint32_t& r0, uint32_t& r1,
                                        uint32_t& r2, uint32_t& r3, uint32_t a) {
    asm volatile("ldmatrix.sync.aligned.m8n8.x4.shared.b16 {%0,%1,%2,%3}, [%4];"
                 : "=r"(r0), "=r"(r1), "=r"(r2), "=r"(r3) : "r"(a));
}
__device__ __forceinline__ void ldsm_x2(uint32_t& r0, uint32_t& r1, uint32_t a) {
    asm volatile("ldmatrix.sync.aligned.m8n8.x2.shared.b16 {%0,%1}, [%2];"
                 : "=r"(r0), "=r"(r1) : "r"(a));
}
__device__ __forceinline__ void ldsm_x2_t(uint32_t& r0, uint32_t& r1, uint32_t a) {
    asm volatile("ldmatrix.sync.aligned.m8n8.x2.trans.shared.b16 {%0,%1}, [%2];"
                 : "=r"(r0), "=r"(r1) : "r"(a));
}

// ---------------------------------------------------------------------------
// fp32 -> fp16 conversion (weights + x), once per launch
// ---------------------------------------------------------------------------
__global__ __launch_bounds__(256) void cvt16_kernel(
    const float* __restrict__ s, __half* __restrict__ d, int n)
{
    int i = (blockIdx.x * 256 + threadIdx.x) * 4;
    if (i < n) {
        float4 v = *(const float4*)(s + i);
        *(__half2*)(d + i)     = __floats2half2_rn(v.x, v.y);
        *(__half2*)(d + i + 2) = __floats2half2_rn(v.z, v.w);
    }
}

// ---------------------------------------------------------------------------
// FP16 GEMM: C[M,N] = A[M,K] @ B[K,N] + bias (+ReLU) (C fp32 or fp16)
// BM=128, BN=128, BK=32, 256 threads (8 warps), warp tile 64x32,
// mma m16n8k16, ldmatrix fragments, 3-stage cp.async pipeline.
// ---------------------------------------------------------------------------
#define A_STR 40
#define B_STR 136
#define A_ELE (128 * A_STR)
#define B_ELE (32  * B_STR)
#define STG_ELE (A_ELE + B_ELE)
#define GEMM_SMEM_BYTES (3 * STG_ELE * 2)     // 56832 bytes

__global__ __launch_bounds__(256) void gemm_f16_kernel(
    const __half* __restrict__ A, const __half* __restrict__ B,
    const float* __restrict__ bias, void* __restrict__ Cout,
    int N, int K, int relu, int half_out)
{
    extern __shared__ __half gsm[];

    const int tid  = threadIdx.x;
    const int lane = tid & 31;
    const int warp = tid >> 5;
    const int wm   = (warp >> 2) * 64;
    const int wn   = (warp & 3) * 32;
    const int r    = lane >> 2;
    const int c    = lane & 3;
    const int bm   = blockIdx.y;
    const int bn   = blockIdx.x;

    const __half* Ab = A + (size_t)bm * 128 * K;
    const __half* Bb = B + (size_t)bn * 128;

    uint32_t asAddr[3], bsAddr[3];
    #pragma unroll
    for (int i = 0; i < 3; i++) {
        asAddr[i] = (uint32_t)__cvta_generic_to_shared(gsm + i * STG_ELE);
        bsAddr[i] = asAddr[i] + A_ELE * 2;
    }

    float acc[4][4][4];
    #pragma unroll
    for (int i = 0; i < 4; i++)
        #pragma unroll
        for (int j = 0; j < 4; j++)
            #pragma unroll
            for (int k = 0; k < 4; k++) acc[i][j][k] = 0.0f;

    const int KT = K / 32;

    auto issue = [&](int kk, int b) {
        #pragma unroll
        for (int i = 0; i < 2; i++) {
            int id = tid + i * 256;
            int ar = id >> 2, ac = (id & 3) * 8;
            cp16(asAddr[b] + (uint32_t)(ar * A_STR + ac) * 2,
                 Ab + (size_t)ar * K + kk + ac);
            int br = id >> 4, bc = (id & 15) * 8;
            cp16(bsAddr[b] + (uint32_t)(br * B_STR + bc) * 2,
                 Bb + (size_t)(kk + br) * N + bc);
        }
        cp_commit();
    };

    issue(0, 0);
    if (KT > 1) issue(32, 1);

    const int lrow = lane & 15;
    const int lcol = (lane & 16) ? 8 : 0;

    int buf = 0;
    for (int kt = 0; kt < KT; kt++) {
        if (kt + 1 < KT) {
            asm volatile("cp.async.wait_group 1;\n" ::: "memory");
        } else {
            asm volatile("cp.async.wait_group 0;\n" ::: "memory");
        }
        __syncthreads();
        if (kt + 2 < KT) {
            int nb = buf + 2; if (nb >= 3) nb -= 3;
            issue((kt + 2) * 32, nb);
        }

        #pragma unroll
        for (int ks = 0; ks < 2; ks++) {
            const int k0 = ks * 16;
            uint32_t af[4][4], bf[4][2];
            #pragma unroll
            for (int ma = 0; ma < 4; ma++) {
                uint32_t a = asAddr[buf] +
                    (uint32_t)((wm + ma * 16 + lrow) * A_STR + k0 + lcol) * 2;
                ldsm_x4(af[ma][0], af[ma][1], af[ma][2], af[ma][3], a);
            }
            #pragma unroll
            for (int na = 0; na < 4; na++) {
                uint32_t a = bsAddr[buf] +
                    (uint32_t)((k0 + lrow) * B_STR + wn + na * 8) * 2;
                ldsm_x2_t(bf[na][0], bf[na][1], a);
            }
            #pragma unroll
            for (int ma = 0; ma < 4; ma++)
                #pragma unroll
                for (int na = 0; na < 4; na++)
                    mma_f16(acc[ma][na][0], acc[ma][na][1],
                            acc[ma][na][2], acc[ma][na][3],
                            af[ma][0], af[ma][1], af[ma][2], af[ma][3],
                            bf[na][0], bf[na][1]);
        }
        if (++buf >= 3) buf = 0;
    }

    #pragma unroll
    for (int ma = 0; ma < 4; ma++) {
        const int row0 = bm * 128 + wm + ma * 16 + r;
        #pragma unroll
        for (int na = 0; na < 4; na++) {
            const int col = bn * 128 + wn + na * 8 + 2 * c;
            const float bv0 = bias[col];
            const float bv1 = bias[col + 1];
            float v0 = acc[ma][na][0] + bv0;
            float v1 = acc[ma][na][1] + bv1;
            float v2 = acc[ma][na][2] + bv0;
            float v3 = acc[ma][na][3] + bv1;
            if (relu) {
                v0 = fmaxf(v0, 0.f); v1 = fmaxf(v1, 0.f);
                v2 = fmaxf(v2, 0.f); v3 = fmaxf(v3, 0.f);
            }
            if (half_out) {
                __half* C = (__half*)Cout;
                *(__half2*)(C + (size_t)row0 * N + col)       = __floats2half2_rn(v0, v1);
                *(__half2*)(C + (size_t)(row0 + 8) * N + col) = __floats2half2_rn(v2, v3);
            } else {
                float* C = (float*)Cout;
                *(float2*)(C + (size_t)row0 * N + col)       = make_float2(v0, v1);
                *(float2*)(C + (size_t)(row0 + 8) * N + col) = make_float2(v2, v3);
            }
        }
    }
}

// ---------------------------------------------------------------------------
// Flash attention, fp16 mma, fp32 softmax. Register-resident P:
// S-accum (rows r,r+8 x cols 2c,2c+1 per n8 tile) converts directly into the
// m16k16 A-fragment for P@V — no smem round-trip, no mid-tile syncwarp.
// Block: 128 q-rows, 256 threads (8 warps x 16 rows). K/V tile: 64 keys.
// ---------------------------------------------------------------------------
#define ATT_QT  128
#define ATT_KT  64
#define AKS_STR 72
#define KV_ELE  (ATT_KT * AKS_STR)
#define PS_ELE  (ATT_QT * AKS_STR)
#define ATT_SMEM_BYTES ((4 * KV_ELE + PS_ELE) * 2)   // 55296

__global__ __launch_bounds__(256, 2) void attn_f16_kernel(
    const __half* __restrict__ Q, const __half* __restrict__ K,
    const __half* __restrict__ V, __half* __restrict__ O)
{
    extern __shared__ __half smh[];
    __half* Ksb[2] = { smh,              smh + KV_ELE };
    __half* Vsb[2] = { smh + 2 * KV_ELE, smh + 3 * KV_ELE };
    __half* Ps     = smh + 4 * KV_ELE;      // Q staging only

    const int b    = blockIdx.z;
    const int h    = blockIdx.y;
    const int qt   = blockIdx.x;
    const int tid  = threadIdx.x;
    const int lane = tid & 31;
    const int warp = tid >> 5;
    const int r    = lane >> 2;
    const int c    = lane & 3;
    const int wm   = warp * 16;
    const int lrow = lane & 15;
    const int lcol = (lane & 16) ? 8 : 0;

    const size_t qrow0 = (size_t)b * SEQ + (size_t)qt * ATT_QT;
    const __half* Qb = Q + qrow0 * D_MODEL + h * D_K;
    const __half* Kb = K + (size_t)b * SEQ * D_MODEL + h * D_K;
    const __half* Vb = V + (size_t)b * SEQ * D_MODEL + h * D_K;

    uint32_t ksA[2], vsA[2];
    ksA[0] = (uint32_t)__cvta_generic_to_shared(Ksb[0]);
    ksA[1] = (uint32_t)__cvta_generic_to_shared(Ksb[1]);
    vsA[0] = (uint32_t)__cvta_generic_to_shared(Vsb[0]);
    vsA[1] = (uint32_t)__cvta_generic_to_shared(Vsb[1]);
    const uint32_t psB = (uint32_t)__cvta_generic_to_shared(Ps);

    auto issue_kv = [&](int kt, int buf) {
        #pragma unroll
        for (int i = 0; i < 2; i++) {
            int id  = tid + i * 256;
            int row = id >> 3, c8 = (id & 7) * 8;
            const size_t gro = (size_t)(kt * ATT_KT + row) * D_MODEL + c8;
            cp16(ksA[buf] + (uint32_t)(row * AKS_STR + c8) * 2, Kb + gro);
            cp16(vsA[buf] + (uint32_t)(row * AKS_STR + c8) * 2, Vb + gro);
        }
        cp_commit();
    };

    issue_kv(0, 0);

    #pragma unroll
    for (int i = 0; i < 4; i++) {
        int id = tid + i * 256;
        int row = id >> 3, c8 = (id & 7) * 8;
        *(uint4*)&Ps[row * AKS_STR + c8] =
            *(const uint4*)(Qb + (size_t)row * D_MODEL + c8);
    }
    __syncthreads();

    uint32_t qa[4][4];
    #pragma unroll
    for (int ks = 0; ks < 4; ks++) {
        uint32_t a = psB + (uint32_t)((wm + lrow) * AKS_STR + ks * 16 + lcol) * 2;
        ldsm_x4(qa[ks][0], qa[ks][1], qa[ks][2], qa[ks][3], a);
    }

    float oacc[8][4];
    #pragma unroll
    for (int nt = 0; nt < 8; nt++)
        #pragma unroll
        for (int i = 0; i < 4; i++) oacc[nt][i] = 0.0f;

    float m0 = -1e30f, m1 = -1e30f, l0 = 0.0f, l1 = 0.0f;

    const int NT = SEQ / ATT_KT;
    for (int kt = 0; kt < NT; kt++) {
        asm volatile("cp.async.wait_group 0;\n" ::: "memory");
        __syncthreads();
        if (kt + 1 < NT) issue_kv(kt + 1, (kt + 1) & 1);

        const uint32_t ksBuf = ksA[kt & 1];
        const uint32_t vsBuf = vsA[kt & 1];

        // ---- S = Q @ K^T  (raw, scale folded into exp below)
        float sacc[8][4];
        #pragma unroll
        for (int nt = 0; nt < 8; nt++) {
            sacc[nt][0] = sacc[nt][1] = sacc[nt][2] = sacc[nt][3] = 0.0f;
            #pragma unroll
            for (int ks = 0; ks < 4; ks++) {
                uint32_t addr = ksBuf + (uint32_t)(
                    (nt * 8 + (lane & 7)) * AKS_STR + ks * 16 + ((lane & 8) ? 8 : 0)) * 2;
                uint32_t b0, b1;
                ldsm_x2(b0, b1, addr);
                mma_f16(sacc[nt][0], sacc[nt][1], sacc[nt][2], sacc[nt][3],
                        qa[ks][0], qa[ks][1], qa[ks][2], qa[ks][3], b0, b1);
            }
        }

        // ---- online softmax (raw max; scale 0.125 folded into exp arg)
        float tm0 = -1e30f, tm1 = -1e30f;
        #pragma unroll
        for (int nt = 0; nt < 8; nt++) {
            tm0 = fmaxf(tm0, fmaxf(sacc[nt][0], sacc[nt][1]));
            tm1 = fmaxf(tm1, fmaxf(sacc[nt][2], sacc[nt][3]));
        }
        tm0 = fmaxf(tm0, __shfl_xor_sync(0xffffffffu, tm0, 1));
        tm0 = fmaxf(tm0, __shfl_xor_sync(0xffffffffu, tm0, 2));
        tm1 = fmaxf(tm1, __shfl_xor_sync(0xffffffffu, tm1, 1));
        tm1 = fmaxf(tm1, __shfl_xor_sync(0xffffffffu, tm1, 2));

        const float mn0 = fmaxf(m0, tm0 * 0.125f);
        const float mn1 = fmaxf(m1, tm1 * 0.125f);
        const float fac0 = __expf(m0 - mn0);
        const float fac1 = __expf(m1 - mn1);
        m0 = mn0; m1 = mn1;

        // ---- P = exp(S/8 - m), kept in registers as fp16 A-fragments
        uint32_t ph[8][2];
        float ts0 = 0.0f, ts1 = 0.0f;
        #pragma unroll
        for (int nt = 0; nt < 8; nt++) {
            float p0 = __expf(fmaf(sacc[nt][0], 0.125f, -mn0));
            float p1 = __expf(fmaf(sacc[nt][1], 0.125f, -mn0));
            float p2 = __expf(fmaf(sacc[nt][2], 0.125f, -mn1));
            float p3 = __expf(fmaf(sacc[nt][3], 0.125f, -mn1));
            ts0 += p0 + p1;
            ts1 += p2 + p3;
            __half2 h01 = __floats2half2_rn(p0, p1);
            __half2 h23 = __floats2half2_rn(p2, p3);
            ph[nt][0] = *(uint32_t*)&h01;   // rows r    : keys nt*8+2c, +1
            ph[nt][1] = *(uint32_t*)&h23;   // rows r+8  : keys nt*8+2c, +1
        }
        ts0 += __shfl_xor_sync(0xffffffffu, ts0, 1);
        ts0 += __shfl_xor_sync(0xffffffffu, ts0, 2);
        ts1 += __shfl_xor_sync(0xffffffffu, ts1, 1);
        ts1 += __shfl_xor_sync(0xffffffffu, ts1, 2);
        l0 = l0 * fac0 + ts0;
        l1 = l1 * fac1 + ts1;

        #pragma unroll
        for (int nt = 0; nt < 8; nt++) {
            oacc[nt][0] *= fac0; oacc[nt][1] *= fac0;
            oacc[nt][2] *= fac1; oacc[nt][3] *= fac1;
        }

        // ---- O += P @ V : A-frags directly from ph (16 keys per k-step)
        #pragma unroll
        for (int kp = 0; kp < 4; kp++) {
            const uint32_t a0 = ph[2 * kp][0];
            const uint32_t a1 = ph[2 * kp][1];
            const uint32_t a2 = ph[2 * kp + 1][0];
            const uint32_t a3 = ph[2 * kp + 1][1];
            #pragma unroll
            for (int nt = 0; nt < 8; nt++) {
                uint32_t b0, b1;
                ldsm_x2_t(b0, b1,
                          vsBuf + (uint32_t)((kp * 16 + lrow) * AKS_STR + nt * 8) * 2);
                mma_f16(oacc[nt][0], oacc[nt][1], oacc[nt][2], oacc[nt][3],
                        a0, a1, a2, a3, b0, b1);
            }
        }
    }

    const float inv0 = 1.0f / l0;
    const float inv1 = 1.0f / l1;
    __half* Ob = O + qrow0 * D_MODEL + h * D_K;
    #pragma unroll
    for (int nt = 0; nt < 8; nt++) {
        const int col = nt * 8 + c * 2;
        *(__half2*)(Ob + (size_t)(wm + r) * D_MODEL + col) =
            __floats2half2_rn(oacc[nt][0] * inv0, oacc[nt][1] * inv0);
        *(__half2*)(Ob + (size_t)(wm + r + 8) * D_MODEL + col) =
            __floats2half2_rn(oacc[nt][2] * inv1, oacc[nt][3] * inv1);
    }
}

// ---------------------------------------------------------------------------
// Fused residual-add + LayerNorm (+fp16 copy)
// ---------------------------------------------------------------------------
__global__ __launch_bounds__(256) void add_ln_kernel(
    const float* __restrict__ a, const float* __restrict__ b,
    const float* __restrict__ g, const float* __restrict__ beta,
    float* __restrict__ out, __half* __restrict__ out16, int w16)
{
    const int row = blockIdx.x;
    const int tid = threadIdx.x;

    const float4 av = *(const float4*)(a + (size_t)row * D_MODEL + tid * 4);
    const float4 bv = *(const float4*)(b + (size_t)row * D_MODEL + tid * 4);
    float4 v;
    v.x = av.x + bv.x; v.y = av.y + bv.y; v.z = av.z + bv.z; v.w = av.w + bv.w;

    float s  = v.x + v.y + v.z + v.w;
    float sq = v.x * v.x + v.y * v.y + v.z * v.z + v.w * v.w;

    #pragma unroll
    for (int off = 16; off; off >>= 1) {
        s  += __shfl_xor_sync(0xffffffffu, s,  off);
        sq += __shfl_xor_sync(0xffffffffu, sq, off);
    }
    __shared__ float red_s[8], red_q[8];
    if ((tid & 31) == 0) { red_s[tid >> 5] = s; red_q[tid >> 5] = sq; }
    __syncthreads();
    __shared__ float smean, srstd;
    if (tid == 0) {
        float ts = 0.f, tq = 0.f;
        #pragma unroll
        for (int i = 0; i < 8; i++) { ts += red_s[i]; tq += red_q[i]; }
        float mean = ts * (1.0f / D_MODEL);
        float var  = tq * (1.0f / D_MODEL) - mean * mean;
        smean = mean;
        srstd = rsqrtf(var + 1e-5f);
    }
    __syncthreads();
    const float mean = smean, rstd = srstd;

    const float4 gv = *(const float4*)(g    + tid * 4);
    const float4 tv = *(const float4*)(beta + tid * 4);
    float4 o;
    o.x = (v.x - mean) * rstd * gv.x + tv.x;
    o.y = (v.y - mean) * rstd * gv.y + tv.y;
    o.z = (v.z - mean) * rstd * gv.z + tv.z;
    o.w = (v.w - mean) * rstd * gv.w + tv.w;
    *(float4*)(out + (size_t)row * D_MODEL + tid * 4) = o;
    if (w16) {
        *(__half2*)(out16 + (size_t)row * D_MODEL + tid * 4)     = __floats2half2_rn(o.x, o.y);
        *(__half2*)(out16 + (size_t)row * D_MODEL + tid * 4 + 2) = __floats2half2_rn(o.z, o.w);
    }
}

// ---------------------------------------------------------------------------
// Launch
// ---------------------------------------------------------------------------
extern "C" void kernel_launch(void* const* d_in, const int* in_sizes, int n_in,
                              void* d_out, int out_size)
{
    const float* x     = (const float*)d_in[0];
    const float* Wq    = (const float*)d_in[1];
    const float* bq    = (const float*)d_in[2];
    const float* Wk    = (const float*)d_in[3];
    const float* bk    = (const float*)d_in[4];
    const float* Wv    = (const float*)d_in[5];
    const float* bv    = (const float*)d_in[6];
    const float* Wo    = (const float*)d_in[7];
    const float* bo    = (const float*)d_in[8];
    const float* ln1_g = (const float*)d_in[9];
    const float* ln1_b = (const float*)d_in[10];
    const float* W1    = (const float*)d_in[11];
    const float* b1    = (const float*)d_in[12];
    const float* W2    = (const float*)d_in[13];
    const float* b2    = (const float*)d_in[14];
    const float* ln2_g = (const float*)d_in[15];
    const float* ln2_b = (const float*)d_in[16];
    float* out = (float*)d_out;

    float *pPrj, *pH, *pF;
    __half *pX16, *pWq, *pWk, *pWv, *pWo, *pW1, *pW2;
    __half *pQ, *pK, *pV, *pCtx, *pH16, *pMid;
    cudaGetSymbolAddress((void**)&pPrj, g_prj);
    cudaGetSymbolAddress((void**)&pH,   g_h);
    cudaGetSymbolAddress((void**)&pF,   g_f);
    cudaGetSymbolAddress((void**)&pX16, g_x16);
    cudaGetSymbolAddress((void**)&pWq,  g_Wq16);
    cudaGetSymbolAddress((void**)&pWk,  g_Wk16);
    cudaGetSymbolAddress((void**)&pWv,  g_Wv16);
    cudaGetSymbolAddress((void**)&pWo,  g_Wo16);
    cudaGetSymbolAddress((void**)&pW1,  g_W116);
    cudaGetSymbolAddress((void**)&pW2,  g_W216);
    cudaGetSymbolAddress((void**)&pQ,   g_Q16);
    cudaGetSymbolAddress((void**)&pK,   g_K16);
    cudaGetSymbolAddress((void**)&pV,   g_V16);
    cudaGetSymbolAddress((void**)&pCtx, g_ctx);
    cudaGetSymbolAddress((void**)&pH16, g_h16);
    cudaGetSymbolAddress((void**)&pMid, g_mid);

    cudaFuncSetAttribute(gemm_f16_kernel,
                         cudaFuncAttributeMaxDynamicSharedMemorySize,
                         GEMM_SMEM_BYTES);
    cudaFuncSetAttribute(attn_f16_kernel,
                         cudaFuncAttributeMaxDynamicSharedMemorySize,
                         ATT_SMEM_BYTES);

    dim3 blk(256);

    // fp32 -> fp16 conversions
    cvt16_kernel<<<(M_ROWS * D_MODEL) / 1024, blk>>>(x,  pX16, M_ROWS * D_MODEL);
    cvt16_kernel<<<(D_MODEL * D_MODEL) / 1024, blk>>>(Wq, pWq, D_MODEL * D_MODEL);
    cvt16_kernel<<<(D_MODEL * D_MODEL) / 1024, blk>>>(Wk, pWk, D_MODEL * D_MODEL);
    cvt16_kernel<<<(D_MODEL * D_MODEL) / 1024, blk>>>(Wv, pWv, D_MODEL * D_MODEL);
    cvt16_kernel<<<(D_MODEL * D_MODEL) / 1024, blk>>>(Wo, pWo, D_MODEL * D_MODEL);
    cvt16_kernel<<<(D_MODEL * D_FF) / 1024, blk>>>(W1, pW1, D_MODEL * D_FF);
    cvt16_kernel<<<(D_FF * D_MODEL) / 1024, blk>>>(W2, pW2, D_FF * D_MODEL);

    dim3 gProj(D_MODEL / 128, M_ROWS / 128);   // (8, 64)
    dim3 gFF1 (D_FF   / 128, M_ROWS / 128);    // (32, 64)
    dim3 gFF2 (D_MODEL / 128, M_ROWS / 128);
    dim3 gAttn(SEQ / ATT_QT, N_HEADS, BATCH);  // (16, 16, 4)

    // QKV projections (fp16 out)
    gemm_f16_kernel<<<gProj, blk, GEMM_SMEM_BYTES>>>(pX16, pWq, bq, pQ, D_MODEL, D_MODEL, 0, 1);
    gemm_f16_kernel<<<gProj, blk, GEMM_SMEM_BYTES>>>(pX16, pWk, bk, pK, D_MODEL, D_MODEL, 0, 1);
    gemm_f16_kernel<<<gProj, blk, GEMM_SMEM_BYTES>>>(pX16, pWv, bv, pV, D_MODEL, D_MODEL, 0, 1);

    // attention (register-resident P)
    attn_f16_kernel<<<gAttn, blk, ATT_SMEM_BYTES>>>(pQ, pK, pV, pCtx);

    // output projection (fp32 out for LN)
    gemm_f16_kernel<<<gProj, blk, GEMM_SMEM_BYTES>>>(pCtx, pWo, bo, pPrj, D_MODEL, D_MODEL, 0, 0);

    // residual + LN1 (fp32 h + fp16 h16)
    add_ln_kernel<<<M_ROWS, blk>>>(pPrj, x, ln1_g, ln1_b, pH, pH16, 1);

    // FFN
    gemm_f16_kernel<<<gFF1, blk, GEMM_SMEM_BYTES>>>(pH16, pW1, b1, pMid, D_FF, D_MODEL, 1, 1);
    gemm_f16_kernel<<<gFF2, blk, GEMM_SMEM_BYTES>>>(pMid, pW2, b2, pF, D_MODEL, D_FF, 0, 0);

    // residual + LN2 -> output (fp32)
    add_ln_kernel<<<M_ROWS, blk>>>(pF, pH, ln2_g, ln2_b, out, pH16, 0);
}

// round 16
// speedup vs baseline: 1.0399x; 1.0106x over previous
#include <cuda_runtime.h>
#include <cuda_bf16.h>
#include <cuda_fp16.h>
#include <cstdint>
#include <stdint.h>
#include <math.h>

// ---------------------------------------------------------------------------
// Transformer encoder block, fp16 tensor-core path (m16n8k16 mma, fp32 accum).
// Attention: register-resident P. All fp32->fp16 conversions in ONE kernel.
// B=4, S=2048, D=1024, H=16, d_k=64, FFN=4096
// ---------------------------------------------------------------------------

#define D_MODEL 1024
#define N_HEADS 16
#define D_K     64
#define D_FF    4096
#define SEQ     2048
#define BATCH   4
#define M_ROWS  (BATCH * SEQ)          // 8192

// fp32 scratch
__device__ float g_prj[M_ROWS * D_MODEL];
__device__ float g_h  [M_ROWS * D_MODEL];
__device__ float g_f  [M_ROWS * D_MODEL];
// fp16 scratch
__device__ __half g_x16 [M_ROWS * D_MODEL];
__device__ __half g_Wq16[D_MODEL * D_MODEL];
__device__ __half g_Wk16[D_MODEL * D_MODEL];
__device__ __half g_Wv16[D_MODEL * D_MODEL];
__device__ __half g_Wo16[D_MODEL * D_MODEL];
__device__ __half g_W116[D_MODEL * D_FF];
__device__ __half g_W216[D_FF * D_MODEL];
__device__ __half g_Q16 [M_ROWS * D_MODEL];
__device__ __half g_K16 [M_ROWS * D_MODEL];
__device__ __half g_V16 [M_ROWS * D_MODEL];
__device__ __half g_ctx [M_ROWS * D_MODEL];
__device__ __half g_h16 [M_ROWS * D_MODEL];
__device__ __half g_mid [(size_t)M_ROWS * D_FF];

// ---------------------------------------------------------------------------
// primitives
// ---------------------------------------------------------------------------
__device__ __forceinline__ void cp16(uint32_t s, const void* g) {
    asm volatile("cp.async.cg.shared.global [%0], [%1], 16;\n" :: "r"(s), "l"(g));
}
__device__ __forceinline__ void cp_commit() {
    asm volatile("cp.async.commit_group;\n" ::: "memory");
}

__device__ __forceinline__ void mma_f16(
    float& c0, float& c1, float& c2, float& c3,
    uint32_t a0, uint32_t a1, uint32_t a2, uint32_t a3,
    uint32_t b0, uint32_t b1)
{
    asm volatile(
        "mma.sync.aligned.m16n8k16.row.col.f32.f16.f16.f32 "
        "{%0,%1,%2,%3}, {%4,%5,%6,%7}, {%8,%9}, {%0,%1,%2,%3};\n"
        : "+f"(c0), "+f"(c1), "+f"(c2), "+f"(c3)
        : "r"(a0), "r"(a1), "r"(a2), "r"(a3), "r"(b0), "r"(b1));
}

__device__ __forceinline__ void ldsm_x4(uint32_t& r0, uint32_t& r1,
                                        uint32_t& r2, uint32_t& r3, uint32_t a) {
    asm volatile("ldmatrix.sync.aligned.m8n8.x4.shared.b16 {%0,%1,%2,%3}, [%4];"
                 : "=r"(r0), "=r"(r1), "=r"(r2), "=r"(r3) : "r"(a));
}
__device__ __forceinline__ void ldsm_x2(uint32_t& r0, uint32_t& r1, uint32_t a) {
    asm volatile("ldmatrix.sync.aligned.m8n8.x2.shared.b16 {%0,%1}, [%2];"
                 : "=r"(r0), "=r"(r1) : "r"(a));
}
__device__ __forceinline__ void ldsm_x2_t(uint32_t& r0, uint32_t& r1, uint32_t a) {
    asm volatile("ldmatrix.sync.aligned.m8n8.x2.trans.shared.b16 {%0,%1}, [%2];"
                 : "=r"(r0), "=r"(r1) : "r"(a));
}

// ---------------------------------------------------------------------------
// Single fused fp32 -> fp16 conversion kernel for x + all 6 weight matrices.
// Segment sizes are multiples of 1M elements; blocks (1024 elems) never
// straddle a segment boundary.
// ---------------------------------------------------------------------------
#define SEG_X  (M_ROWS * D_MODEL)             // 8388608
#define SEG_W  (D_MODEL * D_MODEL)            // 1048576
#define SEG_FF (D_MODEL * D_FF)               // 4194304
#define CVT_TOTAL (SEG_X + 4 * SEG_W + 2 * SEG_FF)   // 20971520
#define CVT_BLOCKS (CVT_TOTAL / 1024)         // 20480

__global__ __launch_bounds__(256) void cvt_all_kernel(
    const float* __restrict__ x,
    const float* __restrict__ wq, const float* __restrict__ wk,
    const float* __restrict__ wv, const float* __restrict__ wo,
    const float* __restrict__ w1, const float* __restrict__ w2,
    __half* __restrict__ dx,
    __half* __restrict__ dwq, __half* __restrict__ dwk,
    __half* __restrict__ dwv, __half* __restrict__ dwo,
    __half* __restrict__ dw1, __half* __restrict__ dw2)
{
    size_t i = ((size_t)blockIdx.x * 256 + threadIdx.x) * 4;
    const float* s;
    __half* d;
    size_t base;
    if (i < SEG_X)                      { s = x;  d = dx;  base = 0; }
    else if (i < SEG_X + SEG_W)         { s = wq; d = dwq; base = SEG_X; }
    else if (i < SEG_X + 2 * SEG_W)     { s = wk; d = dwk; base = SEG_X + SEG_W; }
    else if (i < SEG_X + 3 * SEG_W)     { s = wv; d = dwv; base = SEG_X + 2 * SEG_W; }
    else if (i < SEG_X + 4 * SEG_W)     { s = wo; d = dwo; base = SEG_X + 3 * SEG_W; }
    else if (i < SEG_X + 4 * SEG_W + SEG_FF)
                                        { s = w1; d = dw1; base = SEG_X + 4 * SEG_W; }
    else                                { s = w2; d = dw2; base = SEG_X + 4 * SEG_W + SEG_FF; }
    size_t j = i - base;
    float4 v = *(const float4*)(s + j);
    *(__half2*)(d + j)     = __floats2half2_rn(v.x, v.y);
    *(__half2*)(d + j + 2) = __floats2half2_rn(v.z, v.w);
}

// ---------------------------------------------------------------------------
// FP16 GEMM: C[M,N] = A[M,K] @ B[K,N] + bias (+ReLU) (C fp32 or fp16)
// BM=128, BN=128, BK=32, 256 threads (8 warps), warp tile 64x32,
// mma m16n8k16, ldmatrix fragments, 3-stage cp.async pipeline.
// ---------------------------------------------------------------------------
#define A_STR 40
#define B_STR 136
#define A_ELE (128 * A_STR)
#define B_ELE (32  * B_STR)
#define STG_ELE (A_ELE + B_ELE)
#define GEMM_SMEM_BYTES (3 * STG_ELE * 2)     // 56832 bytes

__global__ __launch_bounds__(256) void gemm_f16_kernel(
    const __half* __restrict__ A, const __half* __restrict__ B,
    const float* __restrict__ bias, void* __restrict__ Cout,
    int N, int K, int relu, int half_out)
{
    extern __shared__ __half gsm[];

    const int tid  = threadIdx.x;
    const int lane = tid & 31;
    const int warp = tid >> 5;
    const int wm   = (warp >> 2) * 64;
    const int wn   = (warp & 3) * 32;
    const int r    = lane >> 2;
    const int c    = lane & 3;
    const int bm   = blockIdx.y;
    const int bn   = blockIdx.x;

    const __half* Ab = A + (size_t)bm * 128 * K;
    const __half* Bb = B + (size_t)bn * 128;

    uint32_t asAddr[3], bsAddr[3];
    #pragma unroll
    for (int i = 0; i < 3; i++) {
        asAddr[i] = (uint32_t)__cvta_generic_to_shared(gsm + i * STG_ELE);
        bsAddr[i] = asAddr[i] + A_ELE * 2;
    }

    float acc[4][4][4];
    #pragma unroll
    for (int i = 0; i < 4; i++)
        #pragma unroll
        for (int j = 0; j < 4; j++)
            #pragma unroll
            for (int k = 0; k < 4; k++) acc[i][j][k] = 0.0f;

    const int KT = K / 32;

    auto issue = [&](int kk, int b) {
        #pragma unroll
        for (int i = 0; i < 2; i++) {
            int id = tid + i * 256;
            int ar = id >> 2, ac = (id & 3) * 8;
            cp16(asAddr[b] + (uint32_t)(ar * A_STR + ac) * 2,
                 Ab + (size_t)ar * K + kk + ac);
            int br = id >> 4, bc = (id & 15) * 8;
            cp16(bsAddr[b] + (uint32_t)(br * B_STR + bc) * 2,
                 Bb + (size_t)(kk + br) * N + bc);
        }
        cp_commit();
    };

    issue(0, 0);
    if (KT > 1) issue(32, 1);

    const int lrow = lane & 15;
    const int lcol = (lane & 16) ? 8 : 0;

    int buf = 0;
    for (int kt = 0; kt < KT; kt++) {
        if (kt + 1 < KT) {
            asm volatile("cp.async.wait_group 1;\n" ::: "memory");
        } else {
            asm volatile("cp.async.wait_group 0;\n" ::: "memory");
        }
        __syncthreads();
        if (kt + 2 < KT) {
            int nb = buf + 2; if (nb >= 3) nb -= 3;
            issue((kt + 2) * 32, nb);
        }

        #pragma unroll
        for (int ks = 0; ks < 2; ks++) {
            const int k0 = ks * 16;
            uint32_t af[4][4], bf[4][2];
            #pragma unroll
            for (int ma = 0; ma < 4; ma++) {
                uint32_t a = asAddr[buf] +
                    (uint32_t)((wm + ma * 16 + lrow) * A_STR + k0 + lcol) * 2;
                ldsm_x4(af[ma][0], af[ma][1], af[ma][2], af[ma][3], a);
            }
            #pragma unroll
            for (int na = 0; na < 4; na++) {
                uint32_t a = bsAddr[buf] +
                    (uint32_t)((k0 + lrow) * B_STR + wn + na * 8) * 2;
                ldsm_x2_t(bf[na][0], bf[na][1], a);
            }
            #pragma unroll
            for (int ma = 0; ma < 4; ma++)
                #pragma unroll
                for (int na = 0; na < 4; na++)
                    mma_f16(acc[ma][na][0], acc[ma][na][1],
                            acc[ma][na][2], acc[ma][na][3],
                            af[ma][0], af[ma][1], af[ma][2], af[ma][3],
                            bf[na][0], bf[na][1]);
        }
        if (++buf >= 3) buf = 0;
    }

    #pragma unroll
    for (int ma = 0; ma < 4; ma++) {
        const int row0 = bm * 128 + wm + ma * 16 + r;
        #pragma unroll
        for (int na = 0; na < 4; na++) {
            const int col = bn * 128 + wn + na * 8 + 2 * c;
            const float bv0 = bias[col];
            const float bv1 = bias[col + 1];
            float v0 = acc[ma][na][0] + bv0;
            float v1 = acc[ma][na][1] + bv1;
            float v2 = acc[ma][na][2] + bv0;
            float v3 = acc[ma][na][3] + bv1;
            if (relu) {
                v0 = fmaxf(v0, 0.f); v1 = fmaxf(v1, 0.f);
                v2 = fmaxf(v2, 0.f); v3 = fmaxf(v3, 0.f);
            }
            if (half_out) {
                __half* C = (__half*)Cout;
                *(__half2*)(C + (size_t)row0 * N + col)       = __floats2half2_rn(v0, v1);
                *(__half2*)(C + (size_t)(row0 + 8) * N + col) = __floats2half2_rn(v2, v3);
            } else {
                float* C = (float*)Cout;
                *(float2*)(C + (size_t)row0 * N + col)       = make_float2(v0, v1);
                *(float2*)(C + (size_t)(row0 + 8) * N + col) = make_float2(v2, v3);
            }
        }
    }
}

// ---------------------------------------------------------------------------
// Flash attention, fp16 mma, fp32 softmax. Register-resident P.
// Block: 128 q-rows, 256 threads (8 warps x 16 rows). K/V tile: 64 keys.
// ---------------------------------------------------------------------------
#define ATT_QT  128
#define ATT_KT  64
#define AKS_STR 72
#define KV_ELE  (ATT_KT * AKS_STR)
#define PS_ELE  (ATT_QT * AKS_STR)
#define ATT_SMEM_BYTES ((4 * KV_ELE + PS_ELE) * 2)   // 55296

__global__ __launch_bounds__(256, 2) void attn_f16_kernel(
    const __half* __restrict__ Q, const __half* __restrict__ K,
    const __half* __restrict__ V, __half* __restrict__ O)
{
    extern __shared__ __half smh[];
    __half* Ksb[2] = { smh,              smh + KV_ELE };
    __half* Vsb[2] = { smh + 2 * KV_ELE, smh + 3 * KV_ELE };
    __half* Ps     = smh + 4 * KV_ELE;      // Q staging only

    const int b    = blockIdx.z;
    const int h    = blockIdx.y;
    const int qt   = blockIdx.x;
    const int tid  = threadIdx.x;
    const int lane = tid & 31;
    const int warp = tid >> 5;
    const int r    = lane >> 2;
    const int c    = lane & 3;
    const int wm   = warp * 16;
    const int lrow = lane & 15;
    const int lcol = (lane & 16) ? 8 : 0;

    const size_t qrow0 = (size_t)b * SEQ + (size_t)qt * ATT_QT;
    const __half* Qb = Q + qrow0 * D_MODEL + h * D_K;
    const __half* Kb = K + (size_t)b * SEQ * D_MODEL + h * D_K;
    const __half* Vb = V + (size_t)b * SEQ * D_MODEL + h * D_K;

    uint32_t ksA[2], vsA[2];
    ksA[0] = (uint32_t)__cvta_generic_to_shared(Ksb[0]);
    ksA[1] = (uint32_t)__cvta_generic_to_shared(Ksb[1]);
    vsA[0] = (uint32_t)__cvta_generic_to_shared(Vsb[0]);
    vsA[1] = (uint32_t)__cvta_generic_to_shared(Vsb[1]);
    const uint32_t psB = (uint32_t)__cvta_generic_to_shared(Ps);

    auto issue_kv = [&](int kt, int buf) {
        #pragma unroll
        for (int i = 0; i < 2; i++) {
            int id  = tid + i * 256;
            int row = id >> 3, c8 = (id & 7) * 8;
            const size_t gro = (size_t)(kt * ATT_KT + row) * D_MODEL + c8;
            cp16(ksA[buf] + (uint32_t)(row * AKS_STR + c8) * 2, Kb + gro);
            cp16(vsA[buf] + (uint32_t)(row * AKS_STR + c8) * 2, Vb + gro);
        }
        cp_commit();
    };

    issue_kv(0, 0);

    #pragma unroll
    for (int i = 0; i < 4; i++) {
        int id = tid + i * 256;
        int row = id >> 3, c8 = (id & 7) * 8;
        *(uint4*)&Ps[row * AKS_STR + c8] =
            *(const uint4*)(Qb + (size_t)row * D_MODEL + c8);
    }
    __syncthreads();

    uint32_t qa[4][4];
    #pragma unroll
    for (int ks = 0; ks < 4; ks++) {
        uint32_t a = psB + (uint32_t)((wm + lrow) * AKS_STR + ks * 16 + lcol) * 2;
        ldsm_x4(qa[ks][0], qa[ks][1], qa[ks][2], qa[ks][3], a);
    }

    float oacc[8][4];
    #pragma unroll
    for (int nt = 0; nt < 8; nt++)
        #pragma unroll
        for (int i = 0; i < 4; i++) oacc[nt][i] = 0.0f;

    float m0 = -1e30f, m1 = -1e30f, l0 = 0.0f, l1 = 0.0f;

    const int NT = SEQ / ATT_KT;
    for (int kt = 0; kt < NT; kt++) {
        asm volatile("cp.async.wait_group 0;\n" ::: "memory");
        __syncthreads();
        if (kt + 1 < NT) issue_kv(kt + 1, (kt + 1) & 1);

        const uint32_t ksBuf = ksA[kt & 1];
        const uint32_t vsBuf = vsA[kt & 1];

        // ---- S = Q @ K^T  (raw, scale folded into exp below)
        float sacc[8][4];
        #pragma unroll
        for (int nt = 0; nt < 8; nt++) {
            sacc[nt][0] = sacc[nt][1] = sacc[nt][2] = sacc[nt][3] = 0.0f;
            #pragma unroll
            for (int ks = 0; ks < 4; ks++) {
                uint32_t addr = ksBuf + (uint32_t)(
                    (nt * 8 + (lane & 7)) * AKS_STR + ks * 16 + ((lane & 8) ? 8 : 0)) * 2;
                uint32_t b0, b1;
                ldsm_x2(b0, b1, addr);
                mma_f16(sacc[nt][0], sacc[nt][1], sacc[nt][2], sacc[nt][3],
                        qa[ks][0], qa[ks][1], qa[ks][2], qa[ks][3], b0, b1);
            }
        }

        // ---- online softmax (raw max; scale 0.125 folded into exp arg)
        float tm0 = -1e30f, tm1 = -1e30f;
        #pragma unroll
        for (int nt = 0; nt < 8; nt++) {
            tm0 = fmaxf(tm0, fmaxf(sacc[nt][0], sacc[nt][1]));
            tm1 = fmaxf(tm1, fmaxf(sacc[nt][2], sacc[nt][3]));
        }
        tm0 = fmaxf(tm0, __shfl_xor_sync(0xffffffffu, tm0, 1));
        tm0 = fmaxf(tm0, __shfl_xor_sync(0xffffffffu, tm0, 2));
        tm1 = fmaxf(tm1, __shfl_xor_sync(0xffffffffu, tm1, 1));
        tm1 = fmaxf(tm1, __shfl_xor_sync(0xffffffffu, tm1, 2));

        const float mn0 = fmaxf(m0, tm0 * 0.125f);
        const float mn1 = fmaxf(m1, tm1 * 0.125f);
        const float fac0 = __expf(m0 - mn0);
        const float fac1 = __expf(m1 - mn1);
        m0 = mn0; m1 = mn1;

        // ---- P = exp(S/8 - m), kept in registers as fp16 A-fragments
        uint32_t ph[8][2];
        float ts0 = 0.0f, ts1 = 0.0f;
        #pragma unroll
        for (int nt = 0; nt < 8; nt++) {
            float p0 = __expf(fmaf(sacc[nt][0], 0.125f, -mn0));
            float p1 = __expf(fmaf(sacc[nt][1], 0.125f, -mn0));
            float p2 = __expf(fmaf(sacc[nt][2], 0.125f, -mn1));
            float p3 = __expf(fmaf(sacc[nt][3], 0.125f, -mn1));
            ts0 += p0 + p1;
            ts1 += p2 + p3;
            __half2 h01 = __floats2half2_rn(p0, p1);
            __half2 h23 = __floats2half2_rn(p2, p3);
            ph[nt][0] = *(uint32_t*)&h01;
            ph[nt][1] = *(uint32_t*)&h23;
        }
        ts0 += __shfl_xor_sync(0xffffffffu, ts0, 1);
        ts0 += __shfl_xor_sync(0xffffffffu, ts0, 2);
        ts1 += __shfl_xor_sync(0xffffffffu, ts1, 1);
        ts1 += __shfl_xor_sync(0xffffffffu, ts1, 2);
        l0 = l0 * fac0 + ts0;
        l1 = l1 * fac1 + ts1;

        #pragma unroll
        for (int nt = 0; nt < 8; nt++) {
            oacc[nt][0] *= fac0; oacc[nt][1] *= fac0;
            oacc[nt][2] *= fac1; oacc[nt][3] *= fac1;
        }

        // ---- O += P @ V : A-frags directly from ph (16 keys per k-step)
        #pragma unroll
        for (int kp = 0; kp < 4; kp++) {
            const uint32_t a0 = ph[2 * kp][0];
            const uint32_t a1 = ph[2 * kp][1];
            const uint32_t a2 = ph[2 * kp + 1][0];
            const uint32_t a3 = ph[2 * kp + 1][1];
            #pragma unroll
            for (int nt = 0; nt < 8; nt++) {
                uint32_t b0, b1;
                ldsm_x2_t(b0, b1,
                          vsBuf + (uint32_t)((kp * 16 + lrow) * AKS_STR + nt * 8) * 2);
                mma_f16(oacc[nt][0], oacc[nt][1], oacc[nt][2], oacc[nt][3],
                        a0, a1, a2, a3, b0, b1);
            }
        }
    }

    const float inv0 = 1.0f / l0;
    const float inv1 = 1.0f / l1;
    __half* Ob = O + qrow0 * D_MODEL + h * D_K;
    #pragma unroll
    for (int nt = 0; nt < 8; nt++) {
        const int col = nt * 8 + c * 2;
        *(__half2*)(Ob + (size_t)(wm + r) * D_MODEL + col) =
            __floats2half2_rn(oacc[nt][0] * inv0, oacc[nt][1] * inv0);
        *(__half2*)(Ob + (size_t)(wm + r + 8) * D_MODEL + col) =
            __floats2half2_rn(oacc[nt][2] * inv1, oacc[nt][3] * inv1);
    }
}

// ---------------------------------------------------------------------------
// Fused residual-add + LayerNorm (+fp16 copy)
// ---------------------------------------------------------------------------
__global__ __launch_bounds__(256) void add_ln_kernel(
    const float* __restrict__ a, const float* __restrict__ b,
    const float* __restrict__ g, const float* __restrict__ beta,
    float* __restrict__ out, __half* __restrict__ out16, int w16)
{
    const int row = blockIdx.x;
    const int tid = threadIdx.x;

    const float4 av = *(const float4*)(a + (size_t)row * D_MODEL + tid * 4);
    const float4 bv = *(const float4*)(b + (size_t)row * D_MODEL + tid * 4);
    float4 v;
    v.x = av.x + bv.x; v.y = av.y + bv.y; v.z = av.z + bv.z; v.w = av.w + bv.w;

    float s  = v.x + v.y + v.z + v.w;
    float sq = v.x * v.x + v.y * v.y + v.z * v.z + v.w * v.w;

    #pragma unroll
    for (int off = 16; off; off >>= 1) {
        s  += __shfl_xor_sync(0xffffffffu, s,  off);
        sq += __shfl_xor_sync(0xffffffffu, sq, off);
    }
    __shared__ float red_s[8], red_q[8];
    if ((tid & 31) == 0) { red_s[tid >> 5] = s; red_q[tid >> 5] = sq; }
    __syncthreads();
    __shared__ float smean, srstd;
    if (tid == 0) {
        float ts = 0.f, tq = 0.f;
        #pragma unroll
        for (int i = 0; i < 8; i++) { ts += red_s[i]; tq += red_q[i]; }
        float mean = ts * (1.0f / D_MODEL);
        float var  = tq * (1.0f / D_MODEL) - mean * mean;
        smean = mean;
        srstd = rsqrtf(var + 1e-5f);
    }
    __syncthreads();
    const float mean = smean, rstd = srstd;

    const float4 gv = *(const float4*)(g    + tid * 4);
    const float4 tv = *(const float4*)(beta + tid * 4);
    float4 o;
    o.x = (v.x - mean) * rstd * gv.x + tv.x;
    o.y = (v.y - mean) * rstd * gv.y + tv.y;
    o.z = (v.z - mean) * rstd * gv.z + tv.z;
    o.w = (v.w - mean) * rstd * gv.w + tv.w;
    *(float4*)(out + (size_t)row * D_MODEL + tid * 4) = o;
    if (w16) {
        *(__half2*)(out16 + (size_t)row * D_MODEL + tid * 4)     = __floats2half2_rn(o.x, o.y);
        *(__half2*)(out16 + (size_t)row * D_MODEL + tid * 4 + 2) = __floats2half2_rn(o.z, o.w);
    }
}

// ---------------------------------------------------------------------------
// Launch
// ---------------------------------------------------------------------------
extern "C" void kernel_launch(void* const* d_in, const int* in_sizes, int n_in,
                              void* d_out, int out_size)
{
    const float* x     = (const float*)d_in[0];
    const float* Wq    = (const float*)d_in[1];
    const float* bq    = (const float*)d_in[2];
    const float* Wk    = (const float*)d_in[3];
    const float* bk    = (const float*)d_in[4];
    const float* Wv    = (const float*)d_in[5];
    const float* bv    = (const float*)d_in[6];
    const float* Wo    = (const float*)d_in[7];
    const float* bo    = (const float*)d_in[8];
    const float* ln1_g = (const float*)d_in[9];
    const float* ln1_b = (const float*)d_in[10];
    const float* W1    = (const float*)d_in[11];
    const float* b1    = (const float*)d_in[12];
    const float* W2    = (const float*)d_in[13];
    const float* b2    = (const float*)d_in[14];
    const float* ln2_g = (const float*)d_in[15];
    const float* ln2_b = (const float*)d_in[16];
    float* out = (float*)d_out;

    float *pPrj, *pH, *pF;
    __half *pX16, *pWq, *pWk, *pWv, *pWo, *pW1, *pW2;
    __half *pQ, *pK, *pV, *pCtx, *pH16, *pMid;
    cudaGetSymbolAddress((void**)&pPrj, g_prj);
    cudaGetSymbolAddress((void**)&pH,   g_h);
    cudaGetSymbolAddress((void**)&pF,   g_f);
    cudaGetSymbolAddress((void**)&pX16, g_x16);
    cudaGetSymbolAddress((void**)&pWq,  g_Wq16);
    cudaGetSymbolAddress((void**)&pWk,  g_Wk16);
    cudaGetSymbolAddress((void**)&pWv,  g_Wv16);
    cudaGetSymbolAddress((void**)&pWo,  g_Wo16);
    cudaGetSymbolAddress((void**)&pW1,  g_W116);
    cudaGetSymbolAddress((void**)&pW2,  g_W216);
    cudaGetSymbolAddress((void**)&pQ,   g_Q16);
    cudaGetSymbolAddress((void**)&pK,   g_K16);
    cudaGetSymbolAddress((void**)&pV,   g_V16);
    cudaGetSymbolAddress((void**)&pCtx, g_ctx);
    cudaGetSymbolAddress((void**)&pH16, g_h16);
    cudaGetSymbolAddress((void**)&pMid, g_mid);

    cudaFuncSetAttribute(gemm_f16_kernel,
                         cudaFuncAttributeMaxDynamicSharedMemorySize,
                         GEMM_SMEM_BYTES);
    cudaFuncSetAttribute(attn_f16_kernel,
                         cudaFuncAttributeMaxDynamicSharedMemorySize,
                         ATT_SMEM_BYTES);

    dim3 blk(256);

    // single fused fp32 -> fp16 conversion (launch 0)
    cvt_all_kernel<<<CVT_BLOCKS, blk>>>(x, Wq, Wk, Wv, Wo, W1, W2,
                                        pX16, pWq, pWk, pWv, pWo, pW1, pW2);

    dim3 gProj(D_MODEL / 128, M_ROWS / 128);   // (8, 64)
    dim3 gFF1 (D_FF   / 128, M_ROWS / 128);    // (32, 64)
    dim3 gFF2 (D_MODEL / 128, M_ROWS / 128);
    dim3 gAttn(SEQ / ATT_QT, N_HEADS, BATCH);  // (16, 16, 4)

    // QKV projections (launches 1-3)
    gemm_f16_kernel<<<gProj, blk, GEMM_SMEM_BYTES>>>(pX16, pWq, bq, pQ, D_MODEL, D_MODEL, 0, 1);
    gemm_f16_kernel<<<gProj, blk, GEMM_SMEM_BYTES>>>(pX16, pWk, bk, pK, D_MODEL, D_MODEL, 0, 1);
    gemm_f16_kernel<<<gProj, blk, GEMM_SMEM_BYTES>>>(pX16, pWv, bv, pV, D_MODEL, D_MODEL, 0, 1);

    // attention (launch 4)
    attn_f16_kernel<<<gAttn, blk, ATT_SMEM_BYTES>>>(pQ, pK, pV, pCtx);

    // output projection (launch 5 — ncu -s 5 profiles this GEMM)
    gemm_f16_kernel<<<gProj, blk, GEMM_SMEM_BYTES>>>(pCtx, pWo, bo, pPrj, D_MODEL, D_MODEL, 0, 0);

    // residual + LN1
    add_ln_kernel<<<M_ROWS, blk>>>(pPrj, x, ln1_g, ln1_b, pH, pH16, 1);

    // FFN
    gemm_f16_kernel<<<gFF1, blk, GEMM_SMEM_BYTES>>>(pH16, pW1, b1, pMid, D_FF, D_MODEL, 1, 1);
    gemm_f16_kernel<<<gFF2, blk, GEMM_SMEM_BYTES>>>(pMid, pW2, b2, pF, D_MODEL, D_FF, 0, 0);

    // residual + LN2 -> output
    add_ln_kernel<<<M_ROWS, blk>>>(pF, pH, ln2_g, ln2_b, out, pH16, 0);
}